// round 1
// baseline (speedup 1.0000x reference)
#include <cuda_runtime.h>
#include <cuda_bf16.h>
#include <cstdint>

// Nearest-of-16-sorted-qpoints quantizer.
// HBM-bound: 256 MiB in + 256 MiB out. Strategy: float4 vector I/O,
// branchless midpoint-threshold selection chain (15 FSELs per element).
// Tie at exact midpoint picks the LEFT qpoint, matching the reference's
// |x-lo| <= |x-hi| -> lo rule.

__global__ __launch_bounds__(256) void QPointQuantize_kernel(
    const float4* __restrict__ x,
    const float* __restrict__ q,
    float4* __restrict__ out,
    int n4)
{
    // Broadcast-load the 16 qpoints (L1/L2 cached, ~free after first warp)
    float qp[16];
#pragma unroll
    for (int i = 0; i < 16; i++) qp[i] = __ldg(q + i);

    // Decision thresholds: midpoints between adjacent qpoints
    float mid[15];
#pragma unroll
    for (int i = 0; i < 15; i++) mid[i] = 0.5f * (qp[i] + qp[i + 1]);

    int idx = blockIdx.x * blockDim.x + threadIdx.x;
    if (idx >= n4) return;

    float4 v = x[idx];
    float4 o;

    // Branchless selection chain per lane-element.
    // x > mid[i-1] promotes to qp[i]; equality keeps the left point.
#define QZ(OUTF, XV)                                   \
    {                                                  \
        float r = qp[0];                               \
        _Pragma("unroll")                              \
        for (int i = 1; i < 16; i++)                   \
            r = ((XV) > mid[i - 1]) ? qp[i] : r;       \
        OUTF = r;                                      \
    }

    QZ(o.x, v.x);
    QZ(o.y, v.y);
    QZ(o.z, v.z);
    QZ(o.w, v.w);
#undef QZ

    out[idx] = o;
}

extern "C" void kernel_launch(void* const* d_in, const int* in_sizes, int n_in,
                              void* d_out, int out_size)
{
    const float* x = (const float*)d_in[0];   // (64, 1024, 1024) fp32
    const float* q = (const float*)d_in[1];   // (16,) fp32 sorted
    float* out = (float*)d_out;

    int n = in_sizes[0];          // 67,108,864 — divisible by 4
    int n4 = n >> 2;              // 16,777,216 float4s

    int threads = 256;
    int blocks = (n4 + threads - 1) / threads;  // 65,536

    QPointQuantize_kernel<<<blocks, threads>>>(
        (const float4*)x, q, (float4*)out, n4);
}

// round 3
// speedup vs baseline: 1.6497x; 1.6497x over previous
#include <cuda_runtime.h>
#include <cuda_bf16.h>
#include <cstdint>

// Nearest-of-16-sorted-qpoints quantizer, round 2.
// R1 was ALU-bound (alu pipe 72%, DRAM 46.6%): 30 alu ops/element from the
// 15-deep select chain. R2: branchless 4-level binary search (~8 alu ops +
// 4 conflict-free LDS per element) against shared midpoint/qpoint LUTs.
// Result index = #{j : x > mid[j]}  (ties at midpoint -> left point),
// identical semantics to the R1 kernel (rel_err was exactly 0).

__device__ __forceinline__ float quant1(float v, float m7,
                                        const float* __restrict__ s_mid,
                                        const float* __restrict__ s_qp)
{
    int i = (v > m7) ? 8 : 0;              // level 0: uniform register compare
    i += (v > s_mid[i + 3]) ? 4 : 0;       // level 1: LDS (banks 3 or 11)
    i += (v > s_mid[i + 1]) ? 2 : 0;       // level 2: LDS
    i += (v > s_mid[i]) ? 1 : 0;           // level 3: LDS
    return s_qp[i];                         // final LUT: LDS, conflict-free
}

__global__ __launch_bounds__(256) void QPointQuantize_kernel(
    const float4* __restrict__ x,
    const float* __restrict__ q,
    float4* __restrict__ out,
    int n4)
{
    __shared__ float s_qp[16];
    __shared__ float s_mid[16];   // 15 used; banks 0-14, conflict-free

    if (threadIdx.x < 16)
        s_qp[threadIdx.x] = q[threadIdx.x];
    __syncthreads();
    if (threadIdx.x < 15)
        s_mid[threadIdx.x] = 0.5f * (s_qp[threadIdx.x] + s_qp[threadIdx.x + 1]);
    __syncthreads();

    const float m7 = s_mid[7];    // uniform -> register, skips one LDS level

    // 2 float4 per thread, both coalesced; front-batched loads for MLP=2.
    int base = blockIdx.x * (256 * 2) + threadIdx.x;

    if (base + 256 < n4) {
        float4 v0 = x[base];
        float4 v1 = x[base + 256];

        float4 o0, o1;
        o0.x = quant1(v0.x, m7, s_mid, s_qp);
        o0.y = quant1(v0.y, m7, s_mid, s_qp);
        o0.z = quant1(v0.z, m7, s_mid, s_qp);
        o0.w = quant1(v0.w, m7, s_mid, s_qp);
        o1.x = quant1(v1.x, m7, s_mid, s_qp);
        o1.y = quant1(v1.y, m7, s_mid, s_qp);
        o1.z = quant1(v1.z, m7, s_mid, s_qp);
        o1.w = quant1(v1.w, m7, s_mid, s_qp);

        out[base]       = o0;
        out[base + 256] = o1;
    } else {
        // Tail safety (n4 is exactly divisible in this problem, but be safe)
        for (int k = 0; k < 2; k++) {
            int idx = base + k * 256;
            if (idx < n4) {
                float4 v = x[idx];
                float4 o;
                o.x = quant1(v.x, m7, s_mid, s_qp);
                o.y = quant1(v.y, m7, s_mid, s_qp);
                o.z = quant1(v.z, m7, s_mid, s_qp);
                o.w = quant1(v.w, m7, s_mid, s_qp);
                out[idx] = o;
            }
        }
    }
}

extern "C" void kernel_launch(void* const* d_in, const int* in_sizes, int n_in,
                              void* d_out, int out_size)
{
    const float* x = (const float*)d_in[0];   // (64, 1024, 1024) fp32
    const float* q = (const float*)d_in[1];   // (16,) fp32 sorted
    float* out = (float*)d_out;

    int n = in_sizes[0];          // 67,108,864
    int n4 = n >> 2;              // 16,777,216 float4s

    int threads = 256;
    int elems_per_block = threads * 2;                     // 512 float4s
    int blocks = (n4 + elems_per_block - 1) / elems_per_block;  // 32,768

    QPointQuantize_kernel<<<blocks, threads>>>(
        (const float4*)x, q, (float4*)out, n4);
}